// round 1
// baseline (speedup 1.0000x reference)
#include <cuda_runtime.h>
#include <cuda_bf16.h>

// Problem constants (fixed dataset)
#define NN 100000      // nodes
#define NE 1600000     // edges
#define IN_F 128
#define H_F 64
#define C_F 16

// Scratch (static device arrays; no allocation allowed)
__device__ float g_H1[NN * H_F];     // X @ W1
__device__ float g_agg1[NN * H_F];   // scatter target layer 1
__device__ float g_H2[NN * C_F];     // relu(agg1+b1) @ W2

// ---------------------------------------------------------------------------
// zero agg1 (float4 stores)
__global__ void zero_agg1_kernel() {
    int i = blockIdx.x * blockDim.x + threadIdx.x;
    float4* p = reinterpret_cast<float4*>(g_agg1);
    if (i < NN * H_F / 4) p[i] = make_float4(0.f, 0.f, 0.f, 0.f);
}

// ---------------------------------------------------------------------------
// GEMM1: H1[NN,64] = X[NN,128] @ W1[128,64]
// Block: 256 threads, 32 rows per block. smem: X tile 16KB + W1 32KB = 48KB.
__global__ __launch_bounds__(256) void gemm1_kernel(
    const float* __restrict__ X, const float* __restrict__ W1)
{
    __shared__ float Xs[32 * 128];
    __shared__ float Ws[128 * 64];
    const int t = threadIdx.x;
    const int row0 = blockIdx.x * 32;

    // load W1 (8192 floats, 32 per thread), coalesced
    #pragma unroll
    for (int i = 0; i < 32; i++) Ws[t + i * 256] = W1[t + i * 256];

    // load X tile as float4 (1024 float4s, 4 per thread)
    const float4* Xv = reinterpret_cast<const float4*>(X);
    float4* Xsv = reinterpret_cast<float4*>(Xs);
    #pragma unroll
    for (int i = 0; i < 4; i++) {
        int idx = t + i * 256;          // float4 index in tile
        int r = idx >> 5;               // 32 float4 per row
        int c = idx & 31;
        int grow = row0 + r;
        float4 v = make_float4(0.f, 0.f, 0.f, 0.f);
        if (grow < NN) v = Xv[(long long)grow * 32 + c];
        Xsv[idx] = v;
    }
    __syncthreads();

    const int cg = (t & 15) * 4;        // 4 consecutive cols
    const int rg = (t >> 4) * 2;        // 2 rows
    float4 a0 = make_float4(0.f,0.f,0.f,0.f);
    float4 a1 = make_float4(0.f,0.f,0.f,0.f);

    #pragma unroll 8
    for (int k = 0; k < 128; k++) {
        float4 w = *reinterpret_cast<const float4*>(&Ws[k * 64 + cg]);
        float x0 = Xs[rg * 128 + k];
        float x1 = Xs[(rg + 1) * 128 + k];
        a0.x = fmaf(x0, w.x, a0.x); a0.y = fmaf(x0, w.y, a0.y);
        a0.z = fmaf(x0, w.z, a0.z); a0.w = fmaf(x0, w.w, a0.w);
        a1.x = fmaf(x1, w.x, a1.x); a1.y = fmaf(x1, w.y, a1.y);
        a1.z = fmaf(x1, w.z, a1.z); a1.w = fmaf(x1, w.w, a1.w);
    }
    int gr = row0 + rg;
    if (gr < NN)     *reinterpret_cast<float4*>(&g_H1[gr * 64 + cg]) = a0;
    if (gr + 1 < NN) *reinterpret_cast<float4*>(&g_H1[(gr + 1) * 64 + cg]) = a1;
}

// ---------------------------------------------------------------------------
// Scatter layer 1: per edge, agg1[dst] += H1[src] * w  (64 floats/edge)
// 16 threads per edge, one float4 each; vector RED (16B) to L2.
__global__ __launch_bounds__(256) void scatter1_kernel(
    const int* __restrict__ esrc, const int* __restrict__ edst,
    const float* __restrict__ ew)
{
    int idx = blockIdx.x * blockDim.x + threadIdx.x;
    if (idx >= NE * 16) return;
    int e = idx >> 4;
    int q = idx & 15;
    int s = __ldg(&esrc[e]);
    int d = __ldg(&edst[e]);
    float w = __ldg(&ew[e]);
    const float4* H1v = reinterpret_cast<const float4*>(g_H1);
    float4 v = __ldg(&H1v[s * 16 + q]);
    float* p = &g_agg1[d * 64 + q * 4];
    asm volatile("red.global.add.v4.f32 [%0], {%1, %2, %3, %4};"
                 :: "l"(p), "f"(v.x * w), "f"(v.y * w), "f"(v.z * w), "f"(v.w * w)
                 : "memory");
}

// ---------------------------------------------------------------------------
// GEMM2 (fused relu+b1 on input): H2[NN,16] = relu(agg1 + b1) @ W2[64,16]
// Block: 256 threads, 64 rows per block.
__global__ __launch_bounds__(256) void gemm2_kernel(
    const float* __restrict__ b1, const float* __restrict__ W2)
{
    __shared__ float hs[64 * 65];   // padded to kill bank conflicts
    __shared__ float Ws[64 * 16];
    __shared__ float b1s[64];
    const int t = threadIdx.x;
    const int row0 = blockIdx.x * 64;

    if (t < 64) b1s[t] = b1[t];
    #pragma unroll
    for (int i = 0; i < 4; i++) Ws[t + i * 256] = W2[t + i * 256];
    __syncthreads();

    #pragma unroll
    for (int i = 0; i < 16; i++) {
        int idx = t + i * 256;
        int r = idx >> 6;
        int k = idx & 63;
        int gr = row0 + r;
        float v = 0.f;
        if (gr < NN) v = fmaxf(g_agg1[gr * 64 + k] + b1s[k], 0.f);
        hs[r * 65 + k] = v;
    }
    __syncthreads();

    const int r  = t >> 2;          // row 0..63
    const int cg = (t & 3) * 4;     // 4 cols
    float4 acc = make_float4(0.f,0.f,0.f,0.f);
    #pragma unroll
    for (int k = 0; k < 64; k++) {
        float x = hs[r * 65 + k];
        float4 w = *reinterpret_cast<const float4*>(&Ws[k * 16 + cg]);
        acc.x = fmaf(x, w.x, acc.x); acc.y = fmaf(x, w.y, acc.y);
        acc.z = fmaf(x, w.z, acc.z); acc.w = fmaf(x, w.w, acc.w);
    }
    int gr = row0 + r;
    if (gr < NN) *reinterpret_cast<float4*>(&g_H2[gr * 16 + cg]) = acc;
}

// ---------------------------------------------------------------------------
// Init output to broadcast b2 (bias fused into the scatter target)
__global__ void init_out_kernel(float* __restrict__ out, const float* __restrict__ b2) {
    int i = blockIdx.x * blockDim.x + threadIdx.x;
    if (i < NN * C_F) out[i] = __ldg(&b2[i & 15]);
}

// ---------------------------------------------------------------------------
// Scatter layer 2: out[dst] += H2[src] * w  (16 floats/edge, 4 threads/edge)
__global__ __launch_bounds__(256) void scatter2_kernel(
    const int* __restrict__ esrc, const int* __restrict__ edst,
    const float* __restrict__ ew, float* __restrict__ out)
{
    int idx = blockIdx.x * blockDim.x + threadIdx.x;
    if (idx >= NE * 4) return;
    int e = idx >> 2;
    int q = idx & 3;
    int s = __ldg(&esrc[e]);
    int d = __ldg(&edst[e]);
    float w = __ldg(&ew[e]);
    const float4* H2v = reinterpret_cast<const float4*>(g_H2);
    float4 v = __ldg(&H2v[s * 4 + q]);
    float* p = &out[d * 16 + q * 4];
    asm volatile("red.global.add.v4.f32 [%0], {%1, %2, %3, %4};"
                 :: "l"(p), "f"(v.x * w), "f"(v.y * w), "f"(v.z * w), "f"(v.w * w)
                 : "memory");
}

// ---------------------------------------------------------------------------
extern "C" void kernel_launch(void* const* d_in, const int* in_sizes, int n_in,
                              void* d_out, int out_size)
{
    const float* X    = (const float*)d_in[0];
    const float* ew   = (const float*)d_in[1];
    const float* W1   = (const float*)d_in[2];
    const float* b1   = (const float*)d_in[3];
    const float* W2   = (const float*)d_in[4];
    const float* b2   = (const float*)d_in[5];
    const int*   esrc = (const int*)d_in[6];
    const int*   edst = (const int*)d_in[7];
    float* out = (float*)d_out;

    // zero agg1
    zero_agg1_kernel<<<(NN * H_F / 4 + 255) / 256, 256>>>();
    // H1 = X @ W1
    gemm1_kernel<<<(NN + 31) / 32, 256>>>(X, W1);
    // agg1 = scatter-add(H1[src] * w -> dst)
    scatter1_kernel<<<(NE * 16 + 255) / 256, 256>>>(esrc, edst, ew);
    // H2 = relu(agg1 + b1) @ W2
    gemm2_kernel<<<(NN + 63) / 64, 256>>>(b1, W2);
    // out = b2 (broadcast)
    init_out_kernel<<<(NN * C_F + 255) / 256, 256>>>(out, b2);
    // out += scatter-add(H2[src] * w -> dst)
    scatter2_kernel<<<(NE * 4 + 255) / 256, 256>>>(esrc, edst, ew, out);
}

// round 2
// speedup vs baseline: 1.1353x; 1.1353x over previous
#include <cuda_runtime.h>
#include <cuda_bf16.h>

// Problem constants (fixed dataset)
#define NN 100000      // nodes
#define NE 1600000     // edges
#define IN_F 128
#define H_F 64
#define C_F 16
#define NBLK ((NN + 1023) / 1024)   // 98 scan blocks

// Scratch (static device arrays; no allocation allowed)
__device__ float g_H1[NN * H_F];      // X @ W1
__device__ float g_agg1[NN * H_F];    // relu(A @ H1 + b1)
__device__ float g_H2[NN * C_F];      // agg1 @ W2
__device__ int   g_deg[NN];           // in-degree per dst
__device__ int   g_off[NN];           // CSR row offsets (exclusive scan of deg)
__device__ int   g_cursor[NN];        // fill cursor for reorder
__device__ int   g_blocksum[NBLK];
__device__ int   g_blockoff[NBLK];
__device__ int2  g_csr[NE];           // (src, weight-bits) sorted by dst

// ---------------------------------------------------------------------------
// CSR build step 1: zero the degree histogram
__global__ void hist_zero_kernel() {
    int i = blockIdx.x * blockDim.x + threadIdx.x;
    if (i < NN) g_deg[i] = 0;
}

// CSR build step 2: in-degree histogram
__global__ void hist_kernel(const int* __restrict__ edst) {
    int e = blockIdx.x * blockDim.x + threadIdx.x;
    if (e < NE) atomicAdd(&g_deg[__ldg(&edst[e])], 1);
}

// CSR build step 3a: per-block exclusive scan (1024 elems/block)
__global__ __launch_bounds__(1024) void scan1_kernel() {
    __shared__ int warpsums[32];
    int t = threadIdx.x, lane = t & 31, wid = t >> 5;
    int i = blockIdx.x * 1024 + t;
    int v = (i < NN) ? g_deg[i] : 0;
    int s = v;
    #pragma unroll
    for (int o = 1; o < 32; o <<= 1) {
        int nv = __shfl_up_sync(0xffffffffu, s, o);
        if (lane >= o) s += nv;
    }
    if (lane == 31) warpsums[wid] = s;
    __syncthreads();
    if (wid == 0) {
        int ws = warpsums[lane];
        int t2 = ws;
        #pragma unroll
        for (int o = 1; o < 32; o <<= 1) {
            int nv = __shfl_up_sync(0xffffffffu, t2, o);
            if (lane >= o) t2 += nv;
        }
        warpsums[lane] = t2 - ws;                 // exclusive warp prefix
        if (lane == 31) g_blocksum[blockIdx.x] = t2;  // block total
    }
    __syncthreads();
    if (i < NN) g_off[i] = warpsums[wid] + s - v;  // exclusive within block
}

// CSR build step 3b: serial scan of 98 block sums (trivial)
__global__ void scan2_kernel() {
    if (threadIdx.x == 0 && blockIdx.x == 0) {
        int run = 0;
        for (int b = 0; b < NBLK; b++) {
            g_blockoff[b] = run;
            run += g_blocksum[b];
        }
    }
}

// CSR build step 3c: add block offsets; init cursors
__global__ void scan3_kernel() {
    int i = blockIdx.x * blockDim.x + threadIdx.x;
    if (i < NN) {
        int val = g_off[i] + g_blockoff[i >> 10];
        g_off[i] = val;
        g_cursor[i] = val;
    }
}

// CSR build step 4: scatter edges into dst-sorted order
__global__ void reorder_kernel(const int* __restrict__ esrc,
                               const int* __restrict__ edst,
                               const float* __restrict__ ew) {
    int e = blockIdx.x * blockDim.x + threadIdx.x;
    if (e < NE) {
        int d = __ldg(&edst[e]);
        int p = atomicAdd(&g_cursor[d], 1);
        g_csr[p] = make_int2(__ldg(&esrc[e]), __float_as_int(__ldg(&ew[e])));
    }
}

// ---------------------------------------------------------------------------
// GEMM1: H1[NN,64] = X[NN,128] @ W1[128,64]
__global__ __launch_bounds__(256) void gemm1_kernel(
    const float* __restrict__ X, const float* __restrict__ W1)
{
    __shared__ float Xs[32 * 128];
    __shared__ float Ws[128 * 64];
    const int t = threadIdx.x;
    const int row0 = blockIdx.x * 32;

    #pragma unroll
    for (int i = 0; i < 32; i++) Ws[t + i * 256] = W1[t + i * 256];

    const float4* Xv = reinterpret_cast<const float4*>(X);
    float4* Xsv = reinterpret_cast<float4*>(Xs);
    #pragma unroll
    for (int i = 0; i < 4; i++) {
        int idx = t + i * 256;
        int r = idx >> 5;
        int c = idx & 31;
        int grow = row0 + r;
        float4 v = make_float4(0.f, 0.f, 0.f, 0.f);
        if (grow < NN) v = Xv[(long long)grow * 32 + c];
        Xsv[idx] = v;
    }
    __syncthreads();

    const int cg = (t & 15) * 4;
    const int rg = (t >> 4) * 2;
    float4 a0 = make_float4(0.f,0.f,0.f,0.f);
    float4 a1 = make_float4(0.f,0.f,0.f,0.f);

    #pragma unroll 8
    for (int k = 0; k < 128; k++) {
        float4 w = *reinterpret_cast<const float4*>(&Ws[k * 64 + cg]);
        float x0 = Xs[rg * 128 + k];
        float x1 = Xs[(rg + 1) * 128 + k];
        a0.x = fmaf(x0, w.x, a0.x); a0.y = fmaf(x0, w.y, a0.y);
        a0.z = fmaf(x0, w.z, a0.z); a0.w = fmaf(x0, w.w, a0.w);
        a1.x = fmaf(x1, w.x, a1.x); a1.y = fmaf(x1, w.y, a1.y);
        a1.z = fmaf(x1, w.z, a1.z); a1.w = fmaf(x1, w.w, a1.w);
    }
    int gr = row0 + rg;
    if (gr < NN)     *reinterpret_cast<float4*>(&g_H1[gr * 64 + cg]) = a0;
    if (gr + 1 < NN) *reinterpret_cast<float4*>(&g_H1[(gr + 1) * 64 + cg]) = a1;
}

// ---------------------------------------------------------------------------
// Aggregation layer 1 (atomic-free): agg1[n] = relu(sum_in H1[src]*w + b1)
// 16 threads per node, one float4 accumulator each.
__global__ __launch_bounds__(256) void agg1_kernel(const float* __restrict__ b1)
{
    int gt = blockIdx.x * blockDim.x + threadIdx.x;
    int n = gt >> 4;
    int q = gt & 15;
    if (n >= NN) return;
    int start = g_off[n];
    int cnt   = g_deg[n];
    const float4* H1v = reinterpret_cast<const float4*>(g_H1);
    float4 acc = make_float4(0.f, 0.f, 0.f, 0.f);
    for (int j = 0; j < cnt; j++) {
        int2 ed = __ldg(&g_csr[start + j]);
        float w = __int_as_float(ed.y);
        float4 v = __ldg(&H1v[ed.x * 16 + q]);
        acc.x = fmaf(v.x, w, acc.x);
        acc.y = fmaf(v.y, w, acc.y);
        acc.z = fmaf(v.z, w, acc.z);
        acc.w = fmaf(v.w, w, acc.w);
    }
    float4 b = __ldg(&reinterpret_cast<const float4*>(b1)[q]);
    acc.x = fmaxf(acc.x + b.x, 0.f);
    acc.y = fmaxf(acc.y + b.y, 0.f);
    acc.z = fmaxf(acc.z + b.z, 0.f);
    acc.w = fmaxf(acc.w + b.w, 0.f);
    reinterpret_cast<float4*>(g_agg1)[n * 16 + q] = acc;
}

// ---------------------------------------------------------------------------
// GEMM2: H2[NN,16] = agg1[NN,64] @ W2[64,16]   (bias/relu already fused in agg1)
// 128 rows/block, 2 rows x 4 cols per thread, float4 LDS everywhere.
__global__ __launch_bounds__(256) void gemm2_kernel(const float* __restrict__ W2)
{
    __shared__ float hs[128 * 68];   // 68-pad keeps float4 alignment, kills conflicts
    __shared__ float Ws[64 * 16];
    const int t = threadIdx.x;
    const int row0 = blockIdx.x * 128;

    #pragma unroll
    for (int i = 0; i < 4; i++) Ws[t + i * 256] = W2[t + i * 256];

    const float4* Av = reinterpret_cast<const float4*>(g_agg1);
    #pragma unroll
    for (int i = 0; i < 8; i++) {
        int idx = t + i * 256;      // float4 index: 16 per row
        int r = idx >> 4;
        int c = idx & 15;
        int gr = row0 + r;
        float4 v = make_float4(0.f, 0.f, 0.f, 0.f);
        if (gr < NN) v = Av[gr * 16 + c];
        *reinterpret_cast<float4*>(&hs[r * 68 + c * 4]) = v;
    }
    __syncthreads();

    const int rg = (t >> 2) * 2;    // 2 rows per thread
    const int cg = (t & 3) * 4;     // 4 cols
    float4 a0 = make_float4(0.f,0.f,0.f,0.f);
    float4 a1 = make_float4(0.f,0.f,0.f,0.f);
    #pragma unroll
    for (int k = 0; k < 64; k += 4) {
        float4 x0 = *reinterpret_cast<const float4*>(&hs[rg * 68 + k]);
        float4 x1 = *reinterpret_cast<const float4*>(&hs[(rg + 1) * 68 + k]);
        #pragma unroll
        for (int kk = 0; kk < 4; kk++) {
            float4 w = *reinterpret_cast<const float4*>(&Ws[(k + kk) * 16 + cg]);
            float xa = (&x0.x)[kk];
            float xb = (&x1.x)[kk];
            a0.x = fmaf(xa, w.x, a0.x); a0.y = fmaf(xa, w.y, a0.y);
            a0.z = fmaf(xa, w.z, a0.z); a0.w = fmaf(xa, w.w, a0.w);
            a1.x = fmaf(xb, w.x, a1.x); a1.y = fmaf(xb, w.y, a1.y);
            a1.z = fmaf(xb, w.z, a1.z); a1.w = fmaf(xb, w.w, a1.w);
        }
    }
    int gr = row0 + rg;
    if (gr < NN)
        reinterpret_cast<float4*>(g_H2)[gr * 4 + (t & 3)] = a0;
    if (gr + 1 < NN)
        reinterpret_cast<float4*>(g_H2)[(gr + 1) * 4 + (t & 3)] = a1;
}

// ---------------------------------------------------------------------------
// Aggregation layer 2 (atomic-free): out[n] = sum_in H2[src]*w + b2
// 4 threads per node, one float4 each. b2 fused; writes every output element.
__global__ __launch_bounds__(256) void agg2_kernel(
    const float* __restrict__ b2, float* __restrict__ out)
{
    int gt = blockIdx.x * blockDim.x + threadIdx.x;
    int n = gt >> 2;
    int q = gt & 3;
    if (n >= NN) return;
    int start = g_off[n];
    int cnt   = g_deg[n];
    const float4* H2v = reinterpret_cast<const float4*>(g_H2);
    float4 acc = make_float4(0.f, 0.f, 0.f, 0.f);
    for (int j = 0; j < cnt; j++) {
        int2 ed = __ldg(&g_csr[start + j]);
        float w = __int_as_float(ed.y);
        float4 v = __ldg(&H2v[ed.x * 4 + q]);
        acc.x = fmaf(v.x, w, acc.x);
        acc.y = fmaf(v.y, w, acc.y);
        acc.z = fmaf(v.z, w, acc.z);
        acc.w = fmaf(v.w, w, acc.w);
    }
    float4 b = __ldg(&reinterpret_cast<const float4*>(b2)[q]);
    acc.x += b.x; acc.y += b.y; acc.z += b.z; acc.w += b.w;
    reinterpret_cast<float4*>(out)[n * 4 + q] = acc;
}

// ---------------------------------------------------------------------------
extern "C" void kernel_launch(void* const* d_in, const int* in_sizes, int n_in,
                              void* d_out, int out_size)
{
    const float* X    = (const float*)d_in[0];
    const float* ew   = (const float*)d_in[1];
    const float* W1   = (const float*)d_in[2];
    const float* b1   = (const float*)d_in[3];
    const float* W2   = (const float*)d_in[4];
    const float* b2   = (const float*)d_in[5];
    const int*   esrc = (const int*)d_in[6];
    const int*   edst = (const int*)d_in[7];
    float* out = (float*)d_out;

    // ---- CSR build (shared by both layers) ----
    hist_zero_kernel<<<(NN + 255) / 256, 256>>>();
    hist_kernel<<<(NE + 255) / 256, 256>>>(edst);
    scan1_kernel<<<NBLK, 1024>>>();
    scan2_kernel<<<1, 32>>>();
    scan3_kernel<<<(NN + 255) / 256, 256>>>();
    reorder_kernel<<<(NE + 255) / 256, 256>>>(esrc, edst, ew);

    // ---- Layer 1 ----
    gemm1_kernel<<<(NN + 31) / 32, 256>>>(X, W1);
    agg1_kernel<<<(NN * 16 + 255) / 256, 256>>>(b1);

    // ---- Layer 2 ----
    gemm2_kernel<<<(NN + 127) / 128, 256>>>(W2);
    agg2_kernel<<<(NN * 4 + 255) / 256, 256>>>(b2, out);
}

// round 3
// speedup vs baseline: 1.2754x; 1.1234x over previous
#include <cuda_runtime.h>
#include <cuda_fp16.h>
#include <cuda_bf16.h>

// Problem constants (fixed dataset)
#define NN 100000      // nodes
#define NE 1600000     // edges
#define IN_F 128
#define H_F 64
#define C_F 16
#define NBLK ((NN + 1023) / 1024)   // 98 scan blocks

// Scratch (static device arrays; no allocation allowed)
__device__ uint4 g_H1h[NN * 8];       // X @ W1, fp16 (64 halves = 8 uint4 per row)
__device__ float g_H2[NN * C_F];      // fused relu(agg1+b1) @ W2, fp32
__device__ int   g_deg[NN];           // in-degree per dst
__device__ int   g_off[NN];           // CSR row offsets
__device__ int   g_cursor[NN];        // fill cursor for reorder
__device__ int   g_blocksum[NBLK];
__device__ int   g_blockoff[NBLK];
__device__ int2  g_csr[NE];           // (src, weight-bits) sorted by dst

// ---------------------------------------------------------------------------
__global__ void hist_zero_kernel() {
    int i = blockIdx.x * blockDim.x + threadIdx.x;
    if (i < NN) g_deg[i] = 0;
}

__global__ void hist_kernel(const int* __restrict__ edst) {
    int e = blockIdx.x * blockDim.x + threadIdx.x;
    if (e < NE) atomicAdd(&g_deg[__ldg(&edst[e])], 1);
}

// per-block exclusive scan (1024 elems/block)
__global__ __launch_bounds__(1024) void scan1_kernel() {
    __shared__ int warpsums[32];
    int t = threadIdx.x, lane = t & 31, wid = t >> 5;
    int i = blockIdx.x * 1024 + t;
    int v = (i < NN) ? g_deg[i] : 0;
    int s = v;
    #pragma unroll
    for (int o = 1; o < 32; o <<= 1) {
        int nv = __shfl_up_sync(0xffffffffu, s, o);
        if (lane >= o) s += nv;
    }
    if (lane == 31) warpsums[wid] = s;
    __syncthreads();
    if (wid == 0) {
        int ws = warpsums[lane];
        int t2 = ws;
        #pragma unroll
        for (int o = 1; o < 32; o <<= 1) {
            int nv = __shfl_up_sync(0xffffffffu, t2, o);
            if (lane >= o) t2 += nv;
        }
        warpsums[lane] = t2 - ws;
        if (lane == 31) g_blocksum[blockIdx.x] = t2;
    }
    __syncthreads();
    if (i < NN) g_off[i] = warpsums[wid] + s - v;
}

// parallel scan of the 98 block sums (one block of 128 threads)
__global__ __launch_bounds__(128) void scan2_kernel() {
    __shared__ int ws[4];
    int t = threadIdx.x, lane = t & 31, wid = t >> 5;
    int v = (t < NBLK) ? g_blocksum[t] : 0;
    int s = v;
    #pragma unroll
    for (int o = 1; o < 32; o <<= 1) {
        int nv = __shfl_up_sync(0xffffffffu, s, o);
        if (lane >= o) s += nv;
    }
    if (lane == 31) ws[wid] = s;
    __syncthreads();
    int add = 0;
    #pragma unroll
    for (int w = 0; w < 4; w++) if (w < wid) add += ws[w];
    if (t < NBLK) g_blockoff[t] = add + s - v;   // exclusive
}

__global__ void scan3_kernel() {
    int i = blockIdx.x * blockDim.x + threadIdx.x;
    if (i < NN) {
        int val = g_off[i] + g_blockoff[i >> 10];
        g_off[i] = val;
        g_cursor[i] = val;
    }
}

__global__ void reorder_kernel(const int* __restrict__ esrc,
                               const int* __restrict__ edst,
                               const float* __restrict__ ew) {
    int e = blockIdx.x * blockDim.x + threadIdx.x;
    if (e < NE) {
        int d = __ldg(&edst[e]);
        int p = atomicAdd(&g_cursor[d], 1);
        g_csr[p] = make_int2(__ldg(&esrc[e]), __float_as_int(__ldg(&ew[e])));
    }
}

// ---------------------------------------------------------------------------
// GEMM1: H1[NN,64] = X[NN,128] @ W1[128,64], output stored fp16
__global__ __launch_bounds__(256) void gemm1_kernel(
    const float* __restrict__ X, const float* __restrict__ W1)
{
    __shared__ float Xs[32 * 128];
    __shared__ float Ws[128 * 64];
    const int t = threadIdx.x;
    const int row0 = blockIdx.x * 32;

    #pragma unroll
    for (int i = 0; i < 32; i++) Ws[t + i * 256] = W1[t + i * 256];

    const float4* Xv = reinterpret_cast<const float4*>(X);
    float4* Xsv = reinterpret_cast<float4*>(Xs);
    #pragma unroll
    for (int i = 0; i < 4; i++) {
        int idx = t + i * 256;
        int r = idx >> 5;
        int c = idx & 31;
        int grow = row0 + r;
        float4 v = make_float4(0.f, 0.f, 0.f, 0.f);
        if (grow < NN) v = Xv[(long long)grow * 32 + c];
        Xsv[idx] = v;
    }
    __syncthreads();

    const int cg = (t & 15) * 4;
    const int rg = (t >> 4) * 2;
    float4 a0 = make_float4(0.f,0.f,0.f,0.f);
    float4 a1 = make_float4(0.f,0.f,0.f,0.f);

    #pragma unroll 8
    for (int k = 0; k < 128; k++) {
        float4 w = *reinterpret_cast<const float4*>(&Ws[k * 64 + cg]);
        float x0 = Xs[rg * 128 + k];
        float x1 = Xs[(rg + 1) * 128 + k];
        a0.x = fmaf(x0, w.x, a0.x); a0.y = fmaf(x0, w.y, a0.y);
        a0.z = fmaf(x0, w.z, a0.z); a0.w = fmaf(x0, w.w, a0.w);
        a1.x = fmaf(x1, w.x, a1.x); a1.y = fmaf(x1, w.y, a1.y);
        a1.z = fmaf(x1, w.z, a1.z); a1.w = fmaf(x1, w.w, a1.w);
    }
    int gr = row0 + rg;
    __half2* H1 = reinterpret_cast<__half2*>(g_H1h);
    if (gr < NN) {
        H1[gr * 32 + cg / 2]     = __floats2half2_rn(a0.x, a0.y);
        H1[gr * 32 + cg / 2 + 1] = __floats2half2_rn(a0.z, a0.w);
    }
    if (gr + 1 < NN) {
        H1[(gr + 1) * 32 + cg / 2]     = __floats2half2_rn(a1.x, a1.y);
        H1[(gr + 1) * 32 + cg / 2 + 1] = __floats2half2_rn(a1.z, a1.w);
    }
}

// ---------------------------------------------------------------------------
// Fused aggregation + GEMM2:
//   h = relu(sum_in H1[src]*w + b1);  H2[n] = h @ W2
// 8 threads per node (each owns 8 of the 64 features, loaded as one uint4 of
// halves per edge). 256 threads = 32 nodes per block; NN*8 = 800000 = 3125*256
// exactly, so no tail guard is needed.
__global__ __launch_bounds__(256) void agg1_fused_kernel(
    const float* __restrict__ b1, const float* __restrict__ W2)
{
    __shared__ float Ws[64 * 16];      // W2 row-major
    __shared__ float b1s[64];
    __shared__ float hbuf[32 * 68];    // 32 nodes x 64 feats, pad 68 (bank-safe)

    const int t = threadIdx.x;
    #pragma unroll
    for (int i = 0; i < 4; i++) Ws[t + i * 256] = W2[t + i * 256];
    if (t < 64) b1s[t] = b1[t];
    __syncthreads();

    const int gt = blockIdx.x * 256 + t;
    const int n = gt >> 3;             // node
    const int q = gt & 7;              // feature octet 8q..8q+7
    const int g = t >> 3;              // node slot in block

    const int start = g_off[n];
    const int cnt   = g_deg[n];

    float acc[8];
    #pragma unroll
    for (int i = 0; i < 8; i++) acc[i] = 0.f;

    for (int j = 0; j < cnt; j++) {
        int2 ed = __ldg(&g_csr[start + j]);
        float w = __int_as_float(ed.y);
        uint4 v = __ldg(&g_H1h[ed.x * 8 + q]);
        const __half2* hp = reinterpret_cast<const __half2*>(&v);
        #pragma unroll
        for (int i = 0; i < 4; i++) {
            float2 f = __half22float2(hp[i]);
            acc[2*i]   = fmaf(f.x, w, acc[2*i]);
            acc[2*i+1] = fmaf(f.y, w, acc[2*i+1]);
        }
    }

    // bias + relu, publish to smem
    #pragma unroll
    for (int i = 0; i < 8; i++) {
        float h = fmaxf(acc[i] + b1s[q * 8 + i], 0.f);
        hbuf[g * 68 + q * 8 + i] = h;
    }
    __syncwarp();

    // inline GEMM2: this thread computes output cols 2q, 2q+1 for node n
    float p0 = 0.f, p1 = 0.f;
    const float4* hb4 = reinterpret_cast<const float4*>(&hbuf[g * 68]);
    const float2* Ws2 = reinterpret_cast<const float2*>(Ws);
    #pragma unroll
    for (int k4 = 0; k4 < 16; k4++) {
        float4 hv = hb4[k4];
        float2 w0 = Ws2[(k4 * 4 + 0) * 8 + q];
        float2 w1 = Ws2[(k4 * 4 + 1) * 8 + q];
        float2 w2 = Ws2[(k4 * 4 + 2) * 8 + q];
        float2 w3 = Ws2[(k4 * 4 + 3) * 8 + q];
        p0 = fmaf(hv.x, w0.x, p0); p1 = fmaf(hv.x, w0.y, p1);
        p0 = fmaf(hv.y, w1.x, p0); p1 = fmaf(hv.y, w1.y, p1);
        p0 = fmaf(hv.z, w2.x, p0); p1 = fmaf(hv.z, w2.y, p1);
        p0 = fmaf(hv.w, w3.x, p0); p1 = fmaf(hv.w, w3.y, p1);
    }
    reinterpret_cast<float2*>(g_H2)[n * 8 + q] = make_float2(p0, p1);
}

// ---------------------------------------------------------------------------
// Aggregation layer 2: out[n] = sum_in H2[src]*w + b2 (4 threads/node)
__global__ __launch_bounds__(256) void agg2_kernel(
    const float* __restrict__ b2, float* __restrict__ out)
{
    int gt = blockIdx.x * blockDim.x + threadIdx.x;
    int n = gt >> 2;
    int q = gt & 3;
    if (n >= NN) return;
    int start = g_off[n];
    int cnt   = g_deg[n];
    const float4* H2v = reinterpret_cast<const float4*>(g_H2);
    float4 acc = make_float4(0.f, 0.f, 0.f, 0.f);
    for (int j = 0; j < cnt; j++) {
        int2 ed = __ldg(&g_csr[start + j]);
        float w = __int_as_float(ed.y);
        float4 v = __ldg(&H2v[ed.x * 4 + q]);
        acc.x = fmaf(v.x, w, acc.x);
        acc.y = fmaf(v.y, w, acc.y);
        acc.z = fmaf(v.z, w, acc.z);
        acc.w = fmaf(v.w, w, acc.w);
    }
    float4 b = __ldg(&reinterpret_cast<const float4*>(b2)[q]);
    acc.x += b.x; acc.y += b.y; acc.z += b.z; acc.w += b.w;
    reinterpret_cast<float4*>(out)[n * 4 + q] = acc;
}

// ---------------------------------------------------------------------------
extern "C" void kernel_launch(void* const* d_in, const int* in_sizes, int n_in,
                              void* d_out, int out_size)
{
    const float* X    = (const float*)d_in[0];
    const float* ew   = (const float*)d_in[1];
    const float* W1   = (const float*)d_in[2];
    const float* b1   = (const float*)d_in[3];
    const float* W2   = (const float*)d_in[4];
    const float* b2   = (const float*)d_in[5];
    const int*   esrc = (const int*)d_in[6];
    const int*   edst = (const int*)d_in[7];
    float* out = (float*)d_out;

    // ---- CSR build (shared by both layers) ----
    hist_zero_kernel<<<(NN + 255) / 256, 256>>>();
    hist_kernel<<<(NE + 255) / 256, 256>>>(edst);
    scan1_kernel<<<NBLK, 1024>>>();
    scan2_kernel<<<1, 128>>>();
    scan3_kernel<<<(NN + 255) / 256, 256>>>();
    reorder_kernel<<<(NE + 255) / 256, 256>>>(esrc, edst, ew);

    // ---- Layer 1 (GEMM) ----
    gemm1_kernel<<<(NN + 31) / 32, 256>>>(X, W1);
    // ---- Layer 1 aggregation + fused GEMM2 ----
    agg1_fused_kernel<<<NN * 8 / 256, 256>>>(b1, W2);
    // ---- Layer 2 aggregation ----
    agg2_kernel<<<(NN * 4 + 255) / 256, 256>>>(b2, out);
}

// round 4
// speedup vs baseline: 1.7157x; 1.3453x over previous
#include <cuda_runtime.h>
#include <cuda_fp16.h>
#include <cuda_bf16.h>
#include <mma.h>
using namespace nvcuda;

// Problem constants (fixed dataset)
#define NN 100000      // nodes
#define NE 1600000     // edges
#define IN_F 128
#define H_F 64
#define C_F 16
#define NBLK ((NN + 1023) / 1024)   // 98 scan blocks

// Scratch (static device arrays; no allocation allowed)
__device__ uint4 g_H1h[NN * 8];       // X @ W1, fp16 (64 halves = 8 uint4 per row)
__device__ float g_H2[NN * C_F];      // fused relu(agg1+b1) @ W2, fp32
__device__ int   g_deg[NN];           // in-degree per dst
__device__ int   g_off[NN];           // CSR row offsets
__device__ int   g_cursor[NN];        // fill cursor for reorder
__device__ int   g_blocksum[NBLK];
__device__ int2  g_csr[NE];           // (src, weight-bits) sorted by dst

// ---------------------------------------------------------------------------
__global__ void hist_zero_kernel() {
    int i = blockIdx.x * blockDim.x + threadIdx.x;
    if (i < NN) g_deg[i] = 0;
}

__global__ void hist_kernel(const int* __restrict__ edst) {
    int e = blockIdx.x * blockDim.x + threadIdx.x;
    if (e < NE) atomicAdd(&g_deg[__ldg(&edst[e])], 1);
}

// per-block exclusive scan (1024 elems/block); writes per-block totals
__global__ __launch_bounds__(1024) void scan1_kernel() {
    __shared__ int warpsums[32];
    int t = threadIdx.x, lane = t & 31, wid = t >> 5;
    int i = blockIdx.x * 1024 + t;
    int v = (i < NN) ? g_deg[i] : 0;
    int s = v;
    #pragma unroll
    for (int o = 1; o < 32; o <<= 1) {
        int nv = __shfl_up_sync(0xffffffffu, s, o);
        if (lane >= o) s += nv;
    }
    if (lane == 31) warpsums[wid] = s;
    __syncthreads();
    if (wid == 0) {
        int ws = warpsums[lane];
        int t2 = ws;
        #pragma unroll
        for (int o = 1; o < 32; o <<= 1) {
            int nv = __shfl_up_sync(0xffffffffu, t2, o);
            if (lane >= o) t2 += nv;
        }
        warpsums[lane] = t2 - ws;
        if (lane == 31) g_blocksum[blockIdx.x] = t2;
    }
    __syncthreads();
    if (i < NN) g_off[i] = warpsums[wid] + s - v;
}

// scan3 (absorbs old scan2): each block computes its own 1024-group's global
// offset by summing the ≤98 preceding block sums, then finalizes off+cursor.
// 256-thread blocks; all 256 nodes in a block share one 1024-group (256|1024).
__global__ __launch_bounds__(256) void scan3_kernel() {
    __shared__ int s_part[8];
    const int t = threadIdx.x;
    const int grp = blockIdx.x >> 2;        // this block's 1024-group index
    int lane = t & 31, wid = t >> 5;
    // sum blocksum[0..grp) with 256 threads
    int v = (t < grp) ? g_blocksum[t] : 0;  // grp <= 97 < 256
    #pragma unroll
    for (int o = 16; o > 0; o >>= 1) v += __shfl_down_sync(0xffffffffu, v, o);
    if (lane == 0) s_part[wid] = v;
    __syncthreads();
    if (t == 0) {
        int s = 0;
        #pragma unroll
        for (int w = 0; w < 8; w++) s += s_part[w];
        s_part[0] = s;
    }
    __syncthreads();
    const int boff = s_part[0];
    int i = blockIdx.x * 256 + t;
    if (i < NN) {
        int val = g_off[i] + boff;
        g_off[i] = val;
        g_cursor[i] = val;
    }
}

__global__ void reorder_kernel(const int* __restrict__ esrc,
                               const int* __restrict__ edst,
                               const float* __restrict__ ew) {
    int e = blockIdx.x * blockDim.x + threadIdx.x;
    if (e < NE) {
        int d = __ldg(&edst[e]);
        int p = atomicAdd(&g_cursor[d], 1);
        g_csr[p] = make_int2(__ldg(&esrc[e]), __float_as_int(__ldg(&ew[e])));
    }
}

// ---------------------------------------------------------------------------
// GEMM1 (tensor cores): H1[NN,64] = X[NN,128] @ W1[128,64]
// fp16 inputs (converted in smem), fp32 accumulate, fp16 output.
// Block: 256 threads (8 warps), tile M=64, N=64, K=128.
#define XS_LD 136
#define WS_LD 72
__global__ __launch_bounds__(256) void gemm1_kernel(
    const float* __restrict__ X, const float* __restrict__ W1)
{
    __shared__ __align__(16) char smbuf[64 * XS_LD * 2 + 128 * WS_LD * 2];
    __half* Xs = reinterpret_cast<__half*>(smbuf);
    __half* Ws = reinterpret_cast<__half*>(smbuf + 64 * XS_LD * 2);
    float*  Cs = reinterpret_cast<float*>(smbuf);   // overlays Xs after compute

    const int t = threadIdx.x;
    const int row0 = blockIdx.x * 64;

    // Load X tile (64 x 128 fp32 -> fp16), float4-vectorized: 2048 float4
    const float4* Xv = reinterpret_cast<const float4*>(X);
    #pragma unroll
    for (int i = 0; i < 8; i++) {
        int idx = t + i * 256;
        int r = idx >> 5;          // 32 float4 per row
        int c4 = idx & 31;
        int grow = row0 + r;
        float4 v = make_float4(0.f, 0.f, 0.f, 0.f);
        if (grow < NN) v = Xv[(long long)grow * 32 + c4];
        __half2* dst = reinterpret_cast<__half2*>(&Xs[r * XS_LD + c4 * 4]);
        dst[0] = __floats2half2_rn(v.x, v.y);
        dst[1] = __floats2half2_rn(v.z, v.w);
    }
    // Load W1 (128 x 64 fp32 -> fp16): 2048 float4
    const float4* Wv = reinterpret_cast<const float4*>(W1);
    #pragma unroll
    for (int i = 0; i < 8; i++) {
        int idx = t + i * 256;
        int k = idx >> 4;          // 16 float4 per row
        int c4 = idx & 15;
        float4 v = Wv[k * 16 + c4];
        __half2* dst = reinterpret_cast<__half2*>(&Ws[k * WS_LD + c4 * 4]);
        dst[0] = __floats2half2_rn(v.x, v.y);
        dst[1] = __floats2half2_rn(v.z, v.w);
    }
    __syncthreads();

    // 8 warps: warp w -> m_tile = w>>1 (16 rows), n half = (w&1)*32 (two 16-col frags)
    const int w = t >> 5;
    const int m_tile = w >> 1;
    const int n0 = (w & 1) * 32;

    wmma::fragment<wmma::accumulator, 16, 16, 16, float> acc0, acc1;
    wmma::fill_fragment(acc0, 0.f);
    wmma::fill_fragment(acc1, 0.f);

    #pragma unroll
    for (int k = 0; k < 8; k++) {
        wmma::fragment<wmma::matrix_a, 16, 16, 16, __half, wmma::row_major> a;
        wmma::load_matrix_sync(a, Xs + m_tile * 16 * XS_LD + k * 16, XS_LD);
        wmma::fragment<wmma::matrix_b, 16, 16, 16, __half, wmma::row_major> b0, b1;
        wmma::load_matrix_sync(b0, Ws + k * 16 * WS_LD + n0, WS_LD);
        wmma::load_matrix_sync(b1, Ws + k * 16 * WS_LD + n0 + 16, WS_LD);
        wmma::mma_sync(acc0, a, b0, acc0);
        wmma::mma_sync(acc1, a, b1, acc1);
    }
    __syncthreads();   // done reading Xs; safe to overlay Cs

    wmma::store_matrix_sync(Cs + m_tile * 16 * 64 + n0, acc0, 64, wmma::mem_row_major);
    wmma::store_matrix_sync(Cs + m_tile * 16 * 64 + n0 + 16, acc1, 64, wmma::mem_row_major);
    __syncthreads();

    // Convert 64x64 fp32 -> fp16 and write coalesced (2048 half2)
    __half2* H1 = reinterpret_cast<__half2*>(g_H1h);
    #pragma unroll
    for (int i = 0; i < 8; i++) {
        int idx = t + i * 256;
        int r = idx >> 5;          // 32 half2 per row
        int c2 = idx & 31;
        int grow = row0 + r;
        if (grow < NN) {
            float lo = Cs[r * 64 + c2 * 2];
            float hi = Cs[r * 64 + c2 * 2 + 1];
            H1[grow * 32 + c2] = __floats2half2_rn(lo, hi);
        }
    }
}

// ---------------------------------------------------------------------------
// Fused aggregation + GEMM2:
//   h = relu(sum_in H1[src]*w + b1);  H2[n] = h @ W2
// 8 threads per node; NN*8 = 800000 = 3125*256 exactly (no tail guard).
__global__ __launch_bounds__(256) void agg1_fused_kernel(
    const float* __restrict__ b1, const float* __restrict__ W2)
{
    __shared__ float Ws[64 * 16];
    __shared__ float b1s[64];
    __shared__ float hbuf[32 * 68];

    const int t = threadIdx.x;
    #pragma unroll
    for (int i = 0; i < 4; i++) Ws[t + i * 256] = W2[t + i * 256];
    if (t < 64) b1s[t] = b1[t];
    __syncthreads();

    const int gt = blockIdx.x * 256 + t;
    const int n = gt >> 3;
    const int q = gt & 7;
    const int g = t >> 3;

    const int start = g_off[n];
    const int cnt   = g_deg[n];

    float acc[8];
    #pragma unroll
    for (int i = 0; i < 8; i++) acc[i] = 0.f;

    for (int j = 0; j < cnt; j++) {
        int2 ed = __ldg(&g_csr[start + j]);
        float w = __int_as_float(ed.y);
        uint4 v = __ldg(&g_H1h[ed.x * 8 + q]);
        const __half2* hp = reinterpret_cast<const __half2*>(&v);
        #pragma unroll
        for (int i = 0; i < 4; i++) {
            float2 f = __half22float2(hp[i]);
            acc[2*i]   = fmaf(f.x, w, acc[2*i]);
            acc[2*i+1] = fmaf(f.y, w, acc[2*i+1]);
        }
    }

    #pragma unroll
    for (int i = 0; i < 8; i++) {
        float h = fmaxf(acc[i] + b1s[q * 8 + i], 0.f);
        hbuf[g * 68 + q * 8 + i] = h;
    }
    __syncwarp();

    // inline GEMM2: this thread computes output cols 2q, 2q+1 for node n
    float p0 = 0.f, p1 = 0.f;
    const float4* hb4 = reinterpret_cast<const float4*>(&hbuf[g * 68]);
    const float2* Ws2 = reinterpret_cast<const float2*>(Ws);
    #pragma unroll
    for (int k4 = 0; k4 < 16; k4++) {
        float4 hv = hb4[k4];
        float2 w0 = Ws2[(k4 * 4 + 0) * 8 + q];
        float2 w1 = Ws2[(k4 * 4 + 1) * 8 + q];
        float2 w2 = Ws2[(k4 * 4 + 2) * 8 + q];
        float2 w3 = Ws2[(k4 * 4 + 3) * 8 + q];
        p0 = fmaf(hv.x, w0.x, p0); p1 = fmaf(hv.x, w0.y, p1);
        p0 = fmaf(hv.y, w1.x, p0); p1 = fmaf(hv.y, w1.y, p1);
        p0 = fmaf(hv.z, w2.x, p0); p1 = fmaf(hv.z, w2.y, p1);
        p0 = fmaf(hv.w, w3.x, p0); p1 = fmaf(hv.w, w3.y, p1);
    }
    reinterpret_cast<float2*>(g_H2)[n * 8 + q] = make_float2(p0, p1);
}

// ---------------------------------------------------------------------------
// Aggregation layer 2: out[n] = sum_in H2[src]*w + b2 (4 threads/node)
__global__ __launch_bounds__(256) void agg2_kernel(
    const float* __restrict__ b2, float* __restrict__ out)
{
    int gt = blockIdx.x * blockDim.x + threadIdx.x;
    int n = gt >> 2;
    int q = gt & 3;
    if (n >= NN) return;
    int start = g_off[n];
    int cnt   = g_deg[n];
    const float4* H2v = reinterpret_cast<const float4*>(g_H2);
    float4 acc = make_float4(0.f, 0.f, 0.f, 0.f);
    for (int j = 0; j < cnt; j++) {
        int2 ed = __ldg(&g_csr[start + j]);
        float w = __int_as_float(ed.y);
        float4 v = __ldg(&H2v[ed.x * 4 + q]);
        acc.x = fmaf(v.x, w, acc.x);
        acc.y = fmaf(v.y, w, acc.y);
        acc.z = fmaf(v.z, w, acc.z);
        acc.w = fmaf(v.w, w, acc.w);
    }
    float4 b = __ldg(&reinterpret_cast<const float4*>(b2)[q]);
    acc.x += b.x; acc.y += b.y; acc.z += b.z; acc.w += b.w;
    reinterpret_cast<float4*>(out)[n * 4 + q] = acc;
}

// ---------------------------------------------------------------------------
extern "C" void kernel_launch(void* const* d_in, const int* in_sizes, int n_in,
                              void* d_out, int out_size)
{
    const float* X    = (const float*)d_in[0];
    const float* ew   = (const float*)d_in[1];
    const float* W1   = (const float*)d_in[2];
    const float* b1   = (const float*)d_in[3];
    const float* W2   = (const float*)d_in[4];
    const float* b2   = (const float*)d_in[5];
    const int*   esrc = (const int*)d_in[6];
    const int*   edst = (const int*)d_in[7];
    float* out = (float*)d_out;

    // ---- CSR build (shared by both layers) ----
    hist_zero_kernel<<<(NN + 255) / 256, 256>>>();
    hist_kernel<<<(NE + 255) / 256, 256>>>(edst);
    scan1_kernel<<<NBLK, 1024>>>();
    scan3_kernel<<<(NN + 255) / 256, 256>>>();
    reorder_kernel<<<(NE + 255) / 256, 256>>>(esrc, edst, ew);

    // ---- Layer 1 (tensor-core GEMM) ----
    gemm1_kernel<<<(NN + 63) / 64, 256>>>(X, W1);
    // ---- Layer 1 aggregation + fused GEMM2 ----
    agg1_fused_kernel<<<NN * 8 / 256, 256>>>(b1, W2);
    // ---- Layer 2 aggregation ----
    agg2_kernel<<<(NN * 4 + 255) / 256, 256>>>(b2, out);
}

// round 5
// speedup vs baseline: 1.7666x; 1.0296x over previous
#include <cuda_runtime.h>
#include <cuda_fp16.h>
#include <cuda_bf16.h>
#include <mma.h>
using namespace nvcuda;

// Problem constants (fixed dataset)
#define NN 100000      // nodes
#define NE 1600000     // edges
#define IN_F 128
#define H_F 64
#define C_F 16
#define NBLK ((NN + 1023) / 1024)   // 98 scan blocks

// Scratch (static device arrays; no allocation allowed)
__device__ uint4 g_H1h[NN * 8];       // X @ W1, fp16 (64 halves = 8 uint4 per row)
__device__ uint4 g_H2h[NN * 2];       // fused layer-2 features, fp16 (16 halves)
__device__ int   g_deg[NN];           // in-degree per dst
__device__ int   g_off[NN];           // CSR row offsets
__device__ int   g_cursor[NN];        // fill cursor for reorder
__device__ int   g_blocksum[NBLK];
__device__ int2  g_csr[NE];           // (src, weight-bits) sorted by dst

// ---------------------------------------------------------------------------
__global__ void hist_zero_kernel() {
    int i = blockIdx.x * blockDim.x + threadIdx.x;
    if (i < NN) g_deg[i] = 0;
}

__global__ void hist_kernel(const int* __restrict__ edst) {
    int e = blockIdx.x * blockDim.x + threadIdx.x;
    if (e < NE) atomicAdd(&g_deg[__ldg(&edst[e])], 1);
}

// per-block exclusive scan (1024 elems/block); writes per-block totals
__global__ __launch_bounds__(1024) void scan1_kernel() {
    __shared__ int warpsums[32];
    int t = threadIdx.x, lane = t & 31, wid = t >> 5;
    int i = blockIdx.x * 1024 + t;
    int v = (i < NN) ? g_deg[i] : 0;
    int s = v;
    #pragma unroll
    for (int o = 1; o < 32; o <<= 1) {
        int nv = __shfl_up_sync(0xffffffffu, s, o);
        if (lane >= o) s += nv;
    }
    if (lane == 31) warpsums[wid] = s;
    __syncthreads();
    if (wid == 0) {
        int ws = warpsums[lane];
        int t2 = ws;
        #pragma unroll
        for (int o = 1; o < 32; o <<= 1) {
            int nv = __shfl_up_sync(0xffffffffu, t2, o);
            if (lane >= o) t2 += nv;
        }
        warpsums[lane] = t2 - ws;
        if (lane == 31) g_blocksum[blockIdx.x] = t2;
    }
    __syncthreads();
    if (i < NN) g_off[i] = warpsums[wid] + s - v;
}

// finalize: add cross-block offsets (each block redundantly sums <=98 values)
__global__ __launch_bounds__(256) void scan3_kernel() {
    __shared__ int s_part[8];
    const int t = threadIdx.x;
    const int grp = blockIdx.x >> 2;
    int lane = t & 31, wid = t >> 5;
    int v = (t < grp) ? g_blocksum[t] : 0;
    #pragma unroll
    for (int o = 16; o > 0; o >>= 1) v += __shfl_down_sync(0xffffffffu, v, o);
    if (lane == 0) s_part[wid] = v;
    __syncthreads();
    if (t == 0) {
        int s = 0;
        #pragma unroll
        for (int w = 0; w < 8; w++) s += s_part[w];
        s_part[0] = s;
    }
    __syncthreads();
    const int boff = s_part[0];
    int i = blockIdx.x * 256 + t;
    if (i < NN) {
        int val = g_off[i] + boff;
        g_off[i] = val;
        g_cursor[i] = val;
    }
}

__global__ void reorder_kernel(const int* __restrict__ esrc,
                               const int* __restrict__ edst,
                               const float* __restrict__ ew) {
    int e = blockIdx.x * blockDim.x + threadIdx.x;
    if (e < NE) {
        int d = __ldg(&edst[e]);
        int p = atomicAdd(&g_cursor[d], 1);
        g_csr[p] = make_int2(__ldg(&esrc[e]), __float_as_int(__ldg(&ew[e])));
    }
}

// ---------------------------------------------------------------------------
// GEMM1 (tensor cores): H1[NN,64] = X[NN,128] @ W1[128,64]
#define XS_LD 136
#define WS_LD 72
__global__ __launch_bounds__(256) void gemm1_kernel(
    const float* __restrict__ X, const float* __restrict__ W1)
{
    __shared__ __align__(16) char smbuf[64 * XS_LD * 2 + 128 * WS_LD * 2];
    __half* Xs = reinterpret_cast<__half*>(smbuf);
    __half* Ws = reinterpret_cast<__half*>(smbuf + 64 * XS_LD * 2);
    float*  Cs = reinterpret_cast<float*>(smbuf);

    const int t = threadIdx.x;
    const int row0 = blockIdx.x * 64;

    const float4* Xv = reinterpret_cast<const float4*>(X);
    #pragma unroll
    for (int i = 0; i < 8; i++) {
        int idx = t + i * 256;
        int r = idx >> 5;
        int c4 = idx & 31;
        int grow = row0 + r;
        float4 v = make_float4(0.f, 0.f, 0.f, 0.f);
        if (grow < NN) v = Xv[(long long)grow * 32 + c4];
        __half2* dst = reinterpret_cast<__half2*>(&Xs[r * XS_LD + c4 * 4]);
        dst[0] = __floats2half2_rn(v.x, v.y);
        dst[1] = __floats2half2_rn(v.z, v.w);
    }
    const float4* Wv = reinterpret_cast<const float4*>(W1);
    #pragma unroll
    for (int i = 0; i < 8; i++) {
        int idx = t + i * 256;
        int k = idx >> 4;
        int c4 = idx & 15;
        float4 v = Wv[k * 16 + c4];
        __half2* dst = reinterpret_cast<__half2*>(&Ws[k * WS_LD + c4 * 4]);
        dst[0] = __floats2half2_rn(v.x, v.y);
        dst[1] = __floats2half2_rn(v.z, v.w);
    }
    __syncthreads();

    const int w = t >> 5;
    const int m_tile = w >> 1;
    const int n0 = (w & 1) * 32;

    wmma::fragment<wmma::accumulator, 16, 16, 16, float> acc0, acc1;
    wmma::fill_fragment(acc0, 0.f);
    wmma::fill_fragment(acc1, 0.f);

    #pragma unroll
    for (int k = 0; k < 8; k++) {
        wmma::fragment<wmma::matrix_a, 16, 16, 16, __half, wmma::row_major> a;
        wmma::load_matrix_sync(a, Xs + m_tile * 16 * XS_LD + k * 16, XS_LD);
        wmma::fragment<wmma::matrix_b, 16, 16, 16, __half, wmma::row_major> b0, b1;
        wmma::load_matrix_sync(b0, Ws + k * 16 * WS_LD + n0, WS_LD);
        wmma::load_matrix_sync(b1, Ws + k * 16 * WS_LD + n0 + 16, WS_LD);
        wmma::mma_sync(acc0, a, b0, acc0);
        wmma::mma_sync(acc1, a, b1, acc1);
    }
    __syncthreads();

    wmma::store_matrix_sync(Cs + m_tile * 16 * 64 + n0, acc0, 64, wmma::mem_row_major);
    wmma::store_matrix_sync(Cs + m_tile * 16 * 64 + n0 + 16, acc1, 64, wmma::mem_row_major);
    __syncthreads();

    __half2* H1 = reinterpret_cast<__half2*>(g_H1h);
    #pragma unroll
    for (int i = 0; i < 8; i++) {
        int idx = t + i * 256;
        int r = idx >> 5;
        int c2 = idx & 31;
        int grow = row0 + r;
        if (grow < NN) {
            float lo = Cs[r * 64 + c2 * 2];
            float hi = Cs[r * 64 + c2 * 2 + 1];
            H1[grow * 32 + c2] = __floats2half2_rn(lo, hi);
        }
    }
}

// ---------------------------------------------------------------------------
// Fused aggregation + GEMM2 with MLP-4 unrolled gather.
// 8 threads per node; NN*8 = 800000 = 3125*256 exactly.
__device__ __forceinline__ void fma_h8(float* acc, uint4 v, float w) {
    const __half2* hp = reinterpret_cast<const __half2*>(&v);
    #pragma unroll
    for (int i = 0; i < 4; i++) {
        float2 f = __half22float2(hp[i]);
        acc[2*i]   = fmaf(f.x, w, acc[2*i]);
        acc[2*i+1] = fmaf(f.y, w, acc[2*i+1]);
    }
}

__global__ __launch_bounds__(256) void agg1_fused_kernel(
    const float* __restrict__ b1, const float* __restrict__ W2)
{
    __shared__ float Ws[64 * 16];
    __shared__ float b1s[64];
    __shared__ float hbuf[32 * 68];

    const int t = threadIdx.x;
    #pragma unroll
    for (int i = 0; i < 4; i++) Ws[t + i * 256] = W2[t + i * 256];
    if (t < 64) b1s[t] = b1[t];
    __syncthreads();

    const int gt = blockIdx.x * 256 + t;
    const int n = gt >> 3;
    const int q = gt & 7;
    const int g = t >> 3;

    const int start = g_off[n];
    const int cnt   = g_deg[n];

    float acc[8];
    #pragma unroll
    for (int i = 0; i < 8; i++) acc[i] = 0.f;

    int j = 0;
    // peel one edge so (start + j) is even -> 16B-aligned int4 CSR loads
    if ((start & 1) && j < cnt) {
        int2 ed = __ldg(&g_csr[start]);
        fma_h8(acc, __ldg(&g_H1h[ed.x * 8 + q]), __int_as_float(ed.y));
        j = 1;
    }
    const int4* csr4 = reinterpret_cast<const int4*>(g_csr + start + j);
    int rem = cnt - j;
    int quads = rem >> 2;
    for (int k = 0; k < quads; k++) {
        int4 eA = __ldg(&csr4[2*k]);       // edges 0,1 of quad
        int4 eB = __ldg(&csr4[2*k + 1]);   // edges 2,3
        uint4 v0 = __ldg(&g_H1h[eA.x * 8 + q]);
        uint4 v1 = __ldg(&g_H1h[eA.z * 8 + q]);
        uint4 v2 = __ldg(&g_H1h[eB.x * 8 + q]);
        uint4 v3 = __ldg(&g_H1h[eB.z * 8 + q]);
        fma_h8(acc, v0, __int_as_float(eA.y));
        fma_h8(acc, v1, __int_as_float(eA.w));
        fma_h8(acc, v2, __int_as_float(eB.y));
        fma_h8(acc, v3, __int_as_float(eB.w));
    }
    j += quads << 2;
    for (; j < cnt; j++) {
        int2 ed = __ldg(&g_csr[start + j]);
        fma_h8(acc, __ldg(&g_H1h[ed.x * 8 + q]), __int_as_float(ed.y));
    }

    #pragma unroll
    for (int i = 0; i < 8; i++) {
        float h = fmaxf(acc[i] + b1s[q * 8 + i], 0.f);
        hbuf[g * 68 + q * 8 + i] = h;
    }
    __syncwarp();

    // inline GEMM2: this thread computes output cols 2q, 2q+1 for node n
    float p0 = 0.f, p1 = 0.f;
    const float4* hb4 = reinterpret_cast<const float4*>(&hbuf[g * 68]);
    const float2* Ws2 = reinterpret_cast<const float2*>(Ws);
    #pragma unroll
    for (int k4 = 0; k4 < 16; k4++) {
        float4 hv = hb4[k4];
        float2 w0 = Ws2[(k4 * 4 + 0) * 8 + q];
        float2 w1 = Ws2[(k4 * 4 + 1) * 8 + q];
        float2 w2 = Ws2[(k4 * 4 + 2) * 8 + q];
        float2 w3 = Ws2[(k4 * 4 + 3) * 8 + q];
        p0 = fmaf(hv.x, w0.x, p0); p1 = fmaf(hv.x, w0.y, p1);
        p0 = fmaf(hv.y, w1.x, p0); p1 = fmaf(hv.y, w1.y, p1);
        p0 = fmaf(hv.z, w2.x, p0); p1 = fmaf(hv.z, w2.y, p1);
        p0 = fmaf(hv.w, w3.x, p0); p1 = fmaf(hv.w, w3.y, p1);
    }
    // store fp16 (halves agg2 gather traffic)
    reinterpret_cast<__half2*>(g_H2h)[n * 8 + q] = __floats2half2_rn(p0, p1);
}

// ---------------------------------------------------------------------------
// Aggregation layer 2: out[n] = sum_in H2[src]*w + b2
// 2 threads per node, each owns 8 halves (one uint4) -> 8 fp32 outputs.
__global__ __launch_bounds__(256) void agg2_kernel(
    const float* __restrict__ b2, float* __restrict__ out)
{
    int gt = blockIdx.x * blockDim.x + threadIdx.x;
    int n = gt >> 1;
    int q = gt & 1;
    if (n >= NN) return;
    const int start = g_off[n];
    const int cnt   = g_deg[n];

    float acc[8];
    #pragma unroll
    for (int i = 0; i < 8; i++) acc[i] = 0.f;

    int j = 0;
    if ((start & 1) && j < cnt) {
        int2 ed = __ldg(&g_csr[start]);
        fma_h8(acc, __ldg(&g_H2h[ed.x * 2 + q]), __int_as_float(ed.y));
        j = 1;
    }
    const int4* csr4 = reinterpret_cast<const int4*>(g_csr + start + j);
    int rem = cnt - j;
    int quads = rem >> 2;
    for (int k = 0; k < quads; k++) {
        int4 eA = __ldg(&csr4[2*k]);
        int4 eB = __ldg(&csr4[2*k + 1]);
        uint4 v0 = __ldg(&g_H2h[eA.x * 2 + q]);
        uint4 v1 = __ldg(&g_H2h[eA.z * 2 + q]);
        uint4 v2 = __ldg(&g_H2h[eB.x * 2 + q]);
        uint4 v3 = __ldg(&g_H2h[eB.z * 2 + q]);
        fma_h8(acc, v0, __int_as_float(eA.y));
        fma_h8(acc, v1, __int_as_float(eA.w));
        fma_h8(acc, v2, __int_as_float(eB.y));
        fma_h8(acc, v3, __int_as_float(eB.w));
    }
    j += quads << 2;
    for (; j < cnt; j++) {
        int2 ed = __ldg(&g_csr[start + j]);
        fma_h8(acc, __ldg(&g_H2h[ed.x * 2 + q]), __int_as_float(ed.y));
    }

    float4 o0, o1;
    const float4* b2v = reinterpret_cast<const float4*>(b2);
    float4 ba = __ldg(&b2v[q * 2]);
    float4 bb = __ldg(&b2v[q * 2 + 1]);
    o0 = make_float4(acc[0] + ba.x, acc[1] + ba.y, acc[2] + ba.z, acc[3] + ba.w);
    o1 = make_float4(acc[4] + bb.x, acc[5] + bb.y, acc[6] + bb.z, acc[7] + bb.w);
    reinterpret_cast<float4*>(out)[n * 4 + q * 2]     = o0;
    reinterpret_cast<float4*>(out)[n * 4 + q * 2 + 1] = o1;
}

// ---------------------------------------------------------------------------
extern "C" void kernel_launch(void* const* d_in, const int* in_sizes, int n_in,
                              void* d_out, int out_size)
{
    const float* X    = (const float*)d_in[0];
    const float* ew   = (const float*)d_in[1];
    const float* W1   = (const float*)d_in[2];
    const float* b1   = (const float*)d_in[3];
    const float* W2   = (const float*)d_in[4];
    const float* b2   = (const float*)d_in[5];
    const int*   esrc = (const int*)d_in[6];
    const int*   edst = (const int*)d_in[7];
    float* out = (float*)d_out;

    // ---- CSR build ----
    hist_zero_kernel<<<(NN + 255) / 256, 256>>>();
    hist_kernel<<<(NE + 255) / 256, 256>>>(edst);
    scan1_kernel<<<NBLK, 1024>>>();
    scan3_kernel<<<(NN + 255) / 256, 256>>>();
    reorder_kernel<<<(NE + 255) / 256, 256>>>(esrc, edst, ew);

    // ---- Layer 1 (tensor-core GEMM) ----
    gemm1_kernel<<<(NN + 63) / 64, 256>>>(X, W1);
    // ---- Layer 1 aggregation + fused GEMM2 ----
    agg1_fused_kernel<<<NN * 8 / 256, 256>>>(b1, W2);
    // ---- Layer 2 aggregation ----
    agg2_kernel<<<(NN * 2 + 255) / 256, 256>>>(b2, out);
}

// round 6
// speedup vs baseline: 1.8372x; 1.0400x over previous
#include <cuda_runtime.h>
#include <cuda_fp16.h>
#include <cuda_bf16.h>
#include <mma.h>
using namespace nvcuda;

// Problem constants (fixed dataset)
#define NN 100000      // nodes
#define NE 1600000     // edges
#define IN_F 128
#define H_F 64
#define C_F 16
#define NBLK ((NN + 1023) / 1024)   // 98 scan blocks

// Scratch (static device arrays; no allocation allowed)
__device__ uint4 g_H1h[NN * 8];       // X @ W1, fp16 (64 halves = 8 uint4 per row)
__device__ uint4 g_H2h[NN * 2];       // fused layer-2 features, fp16 (16 halves)
__device__ int   g_deg[NN];           // in-degree per dst
__device__ int   g_off[NN];           // CSR row offsets
__device__ int   g_cursor[NN];        // fill cursor for reorder
__device__ int   g_blocksum[NBLK];
__device__ int   g_flag[NBLK];        // publication flags for fused scan
__device__ int2  g_csr[NE];           // (src, weight-bits) sorted by dst

// ---------------------------------------------------------------------------
__global__ void hist_zero_kernel() {
    int i = blockIdx.x * blockDim.x + threadIdx.x;
    if (i < NN) g_deg[i] = 0;
    if (i < NBLK) g_flag[i] = 0;
}

__global__ void hist_kernel(const int* __restrict__ edst) {
    int e = blockIdx.x * blockDim.x + threadIdx.x;
    if (e < NE) atomicAdd(&g_deg[__ldg(&edst[e])], 1);
}

// Fused scan: per-block exclusive scan (1024/block) + cross-block lookback.
// All 98 blocks are co-resident (148 SMs), so spin-wait cannot deadlock:
// every block publishes its total BEFORE it spins on predecessors.
__global__ __launch_bounds__(1024) void scan_fused_kernel() {
    __shared__ int warpsums[32];
    __shared__ int s_part[32];
    __shared__ int s_boff;
    const int t = threadIdx.x, lane = t & 31, wid = t >> 5;
    const int b = blockIdx.x;
    const int i = b * 1024 + t;

    int v = (i < NN) ? g_deg[i] : 0;
    int s = v;
    #pragma unroll
    for (int o = 1; o < 32; o <<= 1) {
        int nv = __shfl_up_sync(0xffffffffu, s, o);
        if (lane >= o) s += nv;
    }
    if (lane == 31) warpsums[wid] = s;
    __syncthreads();
    if (wid == 0) {
        int ws = warpsums[lane];
        int t2 = ws;
        #pragma unroll
        for (int o = 1; o < 32; o <<= 1) {
            int nv = __shfl_up_sync(0xffffffffu, t2, o);
            if (lane >= o) t2 += nv;
        }
        warpsums[lane] = t2 - ws;                 // exclusive warp prefix
        if (lane == 31) {                          // publish block total
            g_blocksum[b] = t2;
            __threadfence();
            atomicExch(&g_flag[b], 1);
        }
    }
    __syncthreads();

    // lookback: sum totals of all preceding blocks (b <= 97 < 1024 threads)
    int part = 0;
    if (t < b) {
        while (atomicAdd(&g_flag[t], 0) == 0) { }
        part = g_blocksum[t];
    }
    #pragma unroll
    for (int o = 16; o > 0; o >>= 1) part += __shfl_down_sync(0xffffffffu, part, o);
    if (lane == 0) s_part[wid] = part;
    __syncthreads();
    if (t == 0) {
        int acc = 0;
        #pragma unroll
        for (int w = 0; w < 32; w++) acc += s_part[w];
        s_boff = acc;
    }
    __syncthreads();

    if (i < NN) {
        int val = warpsums[wid] + s - v + s_boff;
        g_off[i] = val;
        g_cursor[i] = val;
    }
}

__global__ void reorder_kernel(const int* __restrict__ esrc,
                               const int* __restrict__ edst,
                               const float* __restrict__ ew) {
    int e = blockIdx.x * blockDim.x + threadIdx.x;
    if (e < NE) {
        int d = __ldg(&edst[e]);
        int p = atomicAdd(&g_cursor[d], 1);
        g_csr[p] = make_int2(__ldg(&esrc[e]), __float_as_int(__ldg(&ew[e])));
    }
}

// ---------------------------------------------------------------------------
// GEMM1 (tensor cores): H1[NN,64] = X[NN,128] @ W1[128,64]
#define XS_LD 136
#define WS_LD 72
__global__ __launch_bounds__(256) void gemm1_kernel(
    const float* __restrict__ X, const float* __restrict__ W1)
{
    __shared__ __align__(16) char smbuf[64 * XS_LD * 2 + 128 * WS_LD * 2];
    __half* Xs = reinterpret_cast<__half*>(smbuf);
    __half* Ws = reinterpret_cast<__half*>(smbuf + 64 * XS_LD * 2);
    float*  Cs = reinterpret_cast<float*>(smbuf);

    const int t = threadIdx.x;
    const int row0 = blockIdx.x * 64;

    const float4* Xv = reinterpret_cast<const float4*>(X);
    #pragma unroll
    for (int i = 0; i < 8; i++) {
        int idx = t + i * 256;
        int r = idx >> 5;
        int c4 = idx & 31;
        int grow = row0 + r;
        float4 v = make_float4(0.f, 0.f, 0.f, 0.f);
        if (grow < NN) v = Xv[(long long)grow * 32 + c4];
        __half2* dst = reinterpret_cast<__half2*>(&Xs[r * XS_LD + c4 * 4]);
        dst[0] = __floats2half2_rn(v.x, v.y);
        dst[1] = __floats2half2_rn(v.z, v.w);
    }
    const float4* Wv = reinterpret_cast<const float4*>(W1);
    #pragma unroll
    for (int i = 0; i < 8; i++) {
        int idx = t + i * 256;
        int k = idx >> 4;
        int c4 = idx & 15;
        float4 v = Wv[k * 16 + c4];
        __half2* dst = reinterpret_cast<__half2*>(&Ws[k * WS_LD + c4 * 4]);
        dst[0] = __floats2half2_rn(v.x, v.y);
        dst[1] = __floats2half2_rn(v.z, v.w);
    }
    __syncthreads();

    const int w = t >> 5;
    const int m_tile = w >> 1;
    const int n0 = (w & 1) * 32;

    wmma::fragment<wmma::accumulator, 16, 16, 16, float> acc0, acc1;
    wmma::fill_fragment(acc0, 0.f);
    wmma::fill_fragment(acc1, 0.f);

    #pragma unroll
    for (int k = 0; k < 8; k++) {
        wmma::fragment<wmma::matrix_a, 16, 16, 16, __half, wmma::row_major> a;
        wmma::load_matrix_sync(a, Xs + m_tile * 16 * XS_LD + k * 16, XS_LD);
        wmma::fragment<wmma::matrix_b, 16, 16, 16, __half, wmma::row_major> b0, b1;
        wmma::load_matrix_sync(b0, Ws + k * 16 * WS_LD + n0, WS_LD);
        wmma::load_matrix_sync(b1, Ws + k * 16 * WS_LD + n0 + 16, WS_LD);
        wmma::mma_sync(acc0, a, b0, acc0);
        wmma::mma_sync(acc1, a, b1, acc1);
    }
    __syncthreads();

    wmma::store_matrix_sync(Cs + m_tile * 16 * 64 + n0, acc0, 64, wmma::mem_row_major);
    wmma::store_matrix_sync(Cs + m_tile * 16 * 64 + n0 + 16, acc1, 64, wmma::mem_row_major);
    __syncthreads();

    __half2* H1 = reinterpret_cast<__half2*>(g_H1h);
    #pragma unroll
    for (int i = 0; i < 8; i++) {
        int idx = t + i * 256;
        int r = idx >> 5;
        int c2 = idx & 31;
        int grow = row0 + r;
        if (grow < NN) {
            float lo = Cs[r * 64 + c2 * 2];
            float hi = Cs[r * 64 + c2 * 2 + 1];
            H1[grow * 32 + c2] = __floats2half2_rn(lo, hi);
        }
    }
}

// ---------------------------------------------------------------------------
__device__ __forceinline__ void fma_h8(float* acc, uint4 v, float w) {
    const __half2* hp = reinterpret_cast<const __half2*>(&v);
    #pragma unroll
    for (int i = 0; i < 4; i++) {
        float2 f = __half22float2(hp[i]);
        acc[2*i]   = fmaf(f.x, w, acc[2*i]);
        acc[2*i+1] = fmaf(f.y, w, acc[2*i+1]);
    }
}

// Fused aggregation + GEMM2. 8 threads per node; NN*8 = 3125*256 exactly.
__global__ __launch_bounds__(256) void agg1_fused_kernel(
    const float* __restrict__ b1, const float* __restrict__ W2)
{
    __shared__ float Ws[64 * 16];
    __shared__ float b1s[64];
    __shared__ float hbuf[32 * 68];

    const int t = threadIdx.x;
    #pragma unroll
    for (int i = 0; i < 4; i++) Ws[t + i * 256] = W2[t + i * 256];
    if (t < 64) b1s[t] = b1[t];
    __syncthreads();

    const int gt = blockIdx.x * 256 + t;
    const int n = gt >> 3;
    const int q = gt & 7;
    const int g = t >> 3;

    const int start = g_off[n];
    const int cnt   = g_deg[n];

    float acc[8];
    #pragma unroll
    for (int i = 0; i < 8; i++) acc[i] = 0.f;

    int j = 0;
    if ((start & 1) && j < cnt) {
        int2 ed = __ldg(&g_csr[start]);
        fma_h8(acc, __ldg(&g_H1h[ed.x * 8 + q]), __int_as_float(ed.y));
        j = 1;
    }
    const int4* csr4 = reinterpret_cast<const int4*>(g_csr + start + j);
    int rem = cnt - j;
    int quads = rem >> 2;
    for (int k = 0; k < quads; k++) {
        int4 eA = __ldg(&csr4[2*k]);
        int4 eB = __ldg(&csr4[2*k + 1]);
        uint4 v0 = __ldg(&g_H1h[eA.x * 8 + q]);
        uint4 v1 = __ldg(&g_H1h[eA.z * 8 + q]);
        uint4 v2 = __ldg(&g_H1h[eB.x * 8 + q]);
        uint4 v3 = __ldg(&g_H1h[eB.z * 8 + q]);
        fma_h8(acc, v0, __int_as_float(eA.y));
        fma_h8(acc, v1, __int_as_float(eA.w));
        fma_h8(acc, v2, __int_as_float(eB.y));
        fma_h8(acc, v3, __int_as_float(eB.w));
    }
    j += quads << 2;
    for (; j < cnt; j++) {
        int2 ed = __ldg(&g_csr[start + j]);
        fma_h8(acc, __ldg(&g_H1h[ed.x * 8 + q]), __int_as_float(ed.y));
    }

    #pragma unroll
    for (int i = 0; i < 8; i++) {
        float h = fmaxf(acc[i] + b1s[q * 8 + i], 0.f);
        hbuf[g * 68 + q * 8 + i] = h;
    }
    __syncwarp();

    float p0 = 0.f, p1 = 0.f;
    const float4* hb4 = reinterpret_cast<const float4*>(&hbuf[g * 68]);
    const float2* Ws2 = reinterpret_cast<const float2*>(Ws);
    #pragma unroll
    for (int k4 = 0; k4 < 16; k4++) {
        float4 hv = hb4[k4];
        float2 w0 = Ws2[(k4 * 4 + 0) * 8 + q];
        float2 w1 = Ws2[(k4 * 4 + 1) * 8 + q];
        float2 w2 = Ws2[(k4 * 4 + 2) * 8 + q];
        float2 w3 = Ws2[(k4 * 4 + 3) * 8 + q];
        p0 = fmaf(hv.x, w0.x, p0); p1 = fmaf(hv.x, w0.y, p1);
        p0 = fmaf(hv.y, w1.x, p0); p1 = fmaf(hv.y, w1.y, p1);
        p0 = fmaf(hv.z, w2.x, p0); p1 = fmaf(hv.z, w2.y, p1);
        p0 = fmaf(hv.w, w3.x, p0); p1 = fmaf(hv.w, w3.y, p1);
    }
    reinterpret_cast<__half2*>(g_H2h)[n * 8 + q] = __floats2half2_rn(p0, p1);
}

// ---------------------------------------------------------------------------
// Aggregation layer 2: out[n] = sum_in H2[src]*w + b2 (2 threads/node)
__global__ __launch_bounds__(256) void agg2_kernel(
    const float* __restrict__ b2, float* __restrict__ out)
{
    int gt = blockIdx.x * blockDim.x + threadIdx.x;
    int n = gt >> 1;
    int q = gt & 1;
    if (n >= NN) return;
    const int start = g_off[n];
    const int cnt   = g_deg[n];

    float acc[8];
    #pragma unroll
    for (int i = 0; i < 8; i++) acc[i] = 0.f;

    int j = 0;
    if ((start & 1) && j < cnt) {
        int2 ed = __ldg(&g_csr[start]);
        fma_h8(acc, __ldg(&g_H2h[ed.x * 2 + q]), __int_as_float(ed.y));
        j = 1;
    }
    const int4* csr4 = reinterpret_cast<const int4*>(g_csr + start + j);
    int rem = cnt - j;
    int quads = rem >> 2;
    for (int k = 0; k < quads; k++) {
        int4 eA = __ldg(&csr4[2*k]);
        int4 eB = __ldg(&csr4[2*k + 1]);
        uint4 v0 = __ldg(&g_H2h[eA.x * 2 + q]);
        uint4 v1 = __ldg(&g_H2h[eA.z * 2 + q]);
        uint4 v2 = __ldg(&g_H2h[eB.x * 2 + q]);
        uint4 v3 = __ldg(&g_H2h[eB.z * 2 + q]);
        fma_h8(acc, v0, __int_as_float(eA.y));
        fma_h8(acc, v1, __int_as_float(eA.w));
        fma_h8(acc, v2, __int_as_float(eB.y));
        fma_h8(acc, v3, __int_as_float(eB.w));
    }
    j += quads << 2;
    for (; j < cnt; j++) {
        int2 ed = __ldg(&g_csr[start + j]);
        fma_h8(acc, __ldg(&g_H2h[ed.x * 2 + q]), __int_as_float(ed.y));
    }

    const float4* b2v = reinterpret_cast<const float4*>(b2);
    float4 ba = __ldg(&b2v[q * 2]);
    float4 bb = __ldg(&b2v[q * 2 + 1]);
    float4 o0 = make_float4(acc[0] + ba.x, acc[1] + ba.y, acc[2] + ba.z, acc[3] + ba.w);
    float4 o1 = make_float4(acc[4] + bb.x, acc[5] + bb.y, acc[6] + bb.z, acc[7] + bb.w);
    reinterpret_cast<float4*>(out)[n * 4 + q * 2]     = o0;
    reinterpret_cast<float4*>(out)[n * 4 + q * 2 + 1] = o1;
}

// ---------------------------------------------------------------------------
extern "C" void kernel_launch(void* const* d_in, const int* in_sizes, int n_in,
                              void* d_out, int out_size)
{
    const float* X    = (const float*)d_in[0];
    const float* ew   = (const float*)d_in[1];
    const float* W1   = (const float*)d_in[2];
    const float* b1   = (const float*)d_in[3];
    const float* W2   = (const float*)d_in[4];
    const float* b2   = (const float*)d_in[5];
    const int*   esrc = (const int*)d_in[6];
    const int*   edst = (const int*)d_in[7];
    float* out = (float*)d_out;

    // Side stream + events, created once on the first (correctness, uncaptured)
    // call; replays issue the identical launch/record/wait sequence every time.
    static cudaStream_t s1 = 0;
    static cudaEvent_t eFork = 0, eJoin = 0;
    static bool init_done = false;
    if (!init_done) {
        cudaStreamCreateWithFlags(&s1, cudaStreamNonBlocking);
        cudaEventCreateWithFlags(&eFork, cudaEventDisableTiming);
        cudaEventCreateWithFlags(&eJoin, cudaEventDisableTiming);
        init_done = true;
    }

    // Fork: gemm1 (independent of CSR build) runs on s1 concurrently
    cudaEventRecord(eFork, 0);
    cudaStreamWaitEvent(s1, eFork, 0);
    gemm1_kernel<<<(NN + 63) / 64, 256, 0, s1>>>(X, W1);

    // CSR build on the main stream (overlaps gemm1)
    hist_zero_kernel<<<(NN + 255) / 256, 256>>>();
    hist_kernel<<<(NE + 255) / 256, 256>>>(edst);
    scan_fused_kernel<<<NBLK, 1024>>>();
    reorder_kernel<<<(NE + 255) / 256, 256>>>(esrc, edst, ew);

    // Join: aggregation needs both H1 and the CSR
    cudaEventRecord(eJoin, s1);
    cudaStreamWaitEvent(0, eJoin, 0);

    agg1_fused_kernel<<<NN * 8 / 256, 256>>>(b1, W2);
    agg2_kernel<<<(NN * 2 + 255) / 256, 256>>>(b2, out);
}